// round 15
// baseline (speedup 1.0000x reference)
#include <cuda_runtime.h>
#include <cstdint>
#include <cstddef>

#define BB 4
#define NN 4096
#define MM 4096
#define CC 128

#define GG 10
#define NCELL (GG*GG)

#define TT 8            // rows per task (row-group)
#define OW 4            // warps per block
#define G  8            // row-group slots per cell
#define NTASK (BB*NCELL*G)    // 3200
#define GRIDA 1184      // 8 blocks/SM * 148 SMs (residency forced by launch_bounds(128,8))

#define THR2 0.04f
#define NEG_INV_SCALE (-99.9999000001f)   /* -(1/(0.01+1e-8)) */

typedef unsigned long long u64;

__device__ __forceinline__ u64 fma2(u64 a, u64 b, u64 c) {
    u64 d; asm("fma.rn.f32x2 %0, %1, %2, %3;" : "=l"(d) : "l"(a), "l"(b), "l"(c)); return d;
}
__device__ __forceinline__ u64 add2(u64 a, u64 b) {
    u64 d; asm("add.rn.f32x2 %0, %1, %2;" : "=l"(d) : "l"(a), "l"(b)); return d;
}
__device__ __forceinline__ u64 pack2(float lo, float hi) {
    u64 d; asm("mov.b64 %0, {%1, %2};" : "=l"(d) : "f"(lo), "f"(hi)); return d;
}

// ---------------- scratch (device globals; no allocation) ----------------
__device__ int    g_mask_i32;

// packed cell-sorted points: (x, y, potential, idx_bits)
__device__ float4 g_spk[BB*NN];   // sources, .z = v (init 0)
__device__ float4 g_tpk[BB*MM];   // targets, .z = u
__device__ int    g_s_cstart[BB][NCELL+1];
__device__ int    g_t_cstart[BB][NCELL+1];

__device__ int    g_nz[BB];       // # target rows with >=1 valid pair
__device__ int    g_ctr[6];       // stealing counters: u0,v0,u1,v1,u2,v2

// barrier state. Sense is READ at kernel entry -> replay-safe for any count.
__device__ int           g_bar_count;
__device__ volatile int  g_bar_sense;

__device__ __forceinline__ void gbar(int* sense) {
    __threadfence();
    __syncthreads();
    if (threadIdx.x == 0) {
        int s = *sense ^ 1;
        *sense = s;
        int a = atomicAdd(&g_bar_count, 1);
        if (a == GRIDA - 1) {
            g_bar_count = 0;
            __threadfence();
            g_bar_sense = s;
        } else {
            while (g_bar_sense != s) __nanosleep(32);
        }
    }
    __syncthreads();
    __threadfence();
}

__device__ __forceinline__ bool mask_at(const void* p, int i) {
    return g_mask_i32 ? (((const int*)p)[i] != 0)
                      : (((const unsigned char*)p)[i] != 0);
}

__device__ __forceinline__ int cell_of(float x, float y) {
    int cx = (int)(x * GG); cx = min(max(cx, 0), GG - 1);
    int cy = (int)(y * GG); cy = min(max(cy, 0), GG - 1);
    return cy * GG + cx;
}

struct SmemSort {
    int hist[4][NCELL];
    int cst[NCELL + 1];
};

// ===== kernel A: init + sort + 3x(u,v), persistent, work-stealing ========
__global__ __launch_bounds__(128, 8) void k_solve(
    const float* __restrict__ slocs,
    const float* __restrict__ tlocs,
    const void*  __restrict__ smask,
    const void*  __restrict__ tmask,
    float* __restrict__ out)
{
    __shared__ SmemSort sms;
    __shared__ float s_red[OW][TT];
    __shared__ int s_flag;
    __shared__ int s_task;
    __shared__ int s_sense0;

    int tid = threadIdx.x, wid = tid >> 5, lane = tid & 31;
    int blk = blockIdx.x;
    const float4 PADC = make_float4(1e30f, 1e30f, 0.f, 0.f);

    if (tid == 0) s_sense0 = g_bar_sense;
    __syncthreads();
    int sense = s_sense0;

    // ================= phase 0: init (detect dtype, zero out) ============
    if (blk == 0) {
        if (tid == 0) s_flag = 0;
        __syncthreads();
        int acc = 0;
        const unsigned char* smb = (const unsigned char*)smask;
        for (int p = tid; p < 16384; p += 128)
            if (p & 3) acc |= smb[p];
        if (acc) atomicOr(&s_flag, 1);
        __syncthreads();
        if (tid == 0) g_mask_i32 = (s_flag == 0);
    } else {
        int gt = (blk - 1) * 128 + tid, nt = (GRIDA - 1) * 128;
        float4* o4 = (float4*)out;
        for (int i = gt; i < BB * MM * (CC / 4); i += nt)
            o4[i] = make_float4(0.f, 0.f, 0.f, 0.f);
        if (gt < BB) g_nz[gt] = 0;
        if (blk == 8 && tid < 6) g_ctr[tid] = 0;
    }
    gbar(&sense);

    // ================= phase 1: sort (blocks 0..7) ========================
    if (blk < 8) {
        int which = blk >> 2, b = blk & 3;
        const void*   mk   = which ? tmask : smask;
        const float2* loc  = (const float2*)(which ? tlocs : slocs);
        float4*       opk  = which ? g_tpk : g_spk;
        int*          cst  = which ? g_t_cstart[b] : g_s_cstart[b];
        int base = b * NN;

        for (int c = tid; c < 4 * NCELL; c += 128) ((int*)sms.hist)[c] = 0;
        __syncthreads();

        int i0w = wid * 1024;
        for (int i0 = i0w; i0 < i0w + 1024; i0 += 32) {
            int i = i0 + lane;
            if (mask_at(mk, base + i)) {
                float2 p = loc[base + i];
                atomicAdd(&sms.hist[wid][cell_of(p.x, p.y)], 1);
            }
        }
        __syncthreads();

        if (tid == 0) {
            int run = 0;
            for (int c = 0; c < NCELL; c++) {
                sms.cst[c] = run;
                int t = 0;
                for (int ww = 0; ww < 4; ww++) t += sms.hist[ww][c];
                run += t;
            }
            sms.cst[NCELL] = run;
            for (int c = 0; c <= NCELL; c++) cst[c] = sms.cst[c];
        }
        __syncthreads();

        if (tid < NCELL) {
            int run = sms.cst[tid];
            for (int ww = 0; ww < 4; ww++) {
                int h = sms.hist[ww][tid];
                sms.hist[ww][tid] = run;
                run += h;
            }
        }
        __syncthreads();

        for (int i0 = i0w; i0 < i0w + 1024; i0 += 32) {
            int i = i0 + lane;
            bool m = mask_at(mk, base + i);
            float2 p = m ? loc[base + i] : make_float2(0.f, 0.f);
            int cell = m ? cell_of(p.x, p.y) : (1000 + lane);
            unsigned peers = __match_any_sync(0xffffffffu, cell);
            if (m) {
                int leader = __ffs(peers) - 1;
                int rank = __popc(peers & ((1u << lane) - 1u));
                int bse = 0;
                if (lane == leader) bse = sms.hist[wid][cell];
                bse = __shfl_sync(peers, bse, leader);
                opk[base + bse + rank] = make_float4(p.x, p.y, 0.f, __int_as_float(i));
                if (lane == leader) sms.hist[wid][cell] = bse + __popc(peers);
            }
        }
    }
    gbar(&sense);

    // ================= 3 Sinkhorn iterations ==============================
    for (int it = 0; it < 3; it++) {
        // ---- u update (branchless inner) ----
        for (;;) {
            __syncthreads();
            if (tid == 0) s_task = atomicAdd(&g_ctr[it * 2], 1);
            __syncthreads();
            int task = s_task;
            if (task >= NTASK) break;
            int g    = task % G;
            int cell = (task / G) % NCELL;
            int b    = task / (G * NCELL);
            int t_lo = g_t_cstart[b][cell], t_hi = g_t_cstart[b][cell + 1];
            int cx = cell % GG, cy = cell / GG;
            int cx0 = max(cx - 2, 0), cx1 = min(cx + 2, GG - 1);
            int cy0 = max(cy - 2, 0), cy1 = min(cy + 2, GG - 1);
            int tbase = b * MM, sbase = b * NN;

            for (int t0 = t_lo + g * TT; t0 < t_hi; t0 += G * TT) {
                int nT = min(TT, t_hi - t0);
                float tx[TT], ty[TT], s[TT];
#pragma unroll
                for (int t = 0; t < TT; t++) {
                    if (t < nT) { float4 tl = g_tpk[tbase + t0 + t]; tx[t] = tl.x; ty[t] = tl.y; }
                    else        { tx[t] = -1e30f; ty[t] = -1e30f; }
                    s[t] = 0.f;
                }
                for (int yy = cy0; yy <= cy1; yy++) {
                    int beg = g_s_cstart[b][yy * GG + cx0];
                    int end = g_s_cstart[b][yy * GG + cx1 + 1];
                    int j0b = beg + wid * 32;
                    if (j0b >= end) continue;
                    int j = j0b + lane;
                    float4 c = (j < end) ? g_spk[sbase + j] : PADC;
                    for (int j0 = j0b; j0 < end; j0 += OW * 32) {
                        int jn = j0 + OW * 32 + lane;
                        float4 nx = (jn < end) ? g_spk[sbase + jn] : PADC;
#pragma unroll
                        for (int t = 0; t < TT; t++) {
                            float dx = tx[t] - c.x, dy = ty[t] - c.y;
                            float d2 = __fadd_rn(__fmul_rn(dx, dx), __fmul_rn(dy, dy));
                            float e = __expf(__fmul_rn(d2, NEG_INV_SCALE) + c.z);
                            s[t] += (d2 < THR2) ? e : 0.f;
                        }
                        c = nx;
                    }
                }
#pragma unroll
                for (int t = 0; t < TT; t++) {
                    float tot = s[t];
                    for (int o = 16; o; o >>= 1) tot += __shfl_xor_sync(0xffffffffu, tot, o);
                    if (lane == 0) s_red[wid][t] = tot;
                }
                __syncthreads();
                if (tid < TT) {
                    float tot = s_red[0][tid] + s_red[1][tid] + s_red[2][tid] + s_red[3][tid];
                    if (tid < nT) {
                        g_tpk[tbase + t0 + tid].z = (tot > 0.f) ? -__logf(tot) : 1e9f;
                        if (it == 0 && tot > 0.f) atomicAdd(&g_nz[b], 1);
                    }
                }
                __syncthreads();
            }
        }
        gbar(&sense);

        // ---- v update (branchless inner) ----
        for (;;) {
            __syncthreads();
            if (tid == 0) s_task = atomicAdd(&g_ctr[it * 2 + 1], 1);
            __syncthreads();
            int task = s_task;
            if (task >= NTASK) break;
            int g    = task % G;
            int cell = (task / G) % NCELL;
            int b    = task / (G * NCELL);
            int s_lo = g_s_cstart[b][cell], s_hi = g_s_cstart[b][cell + 1];
            int cx = cell % GG, cy = cell / GG;
            int cx0 = max(cx - 2, 0), cx1 = min(cx + 2, GG - 1);
            int cy0 = max(cy - 2, 0), cy1 = min(cy + 2, GG - 1);
            int tbase = b * MM, sbase = b * NN;
            float c0 = (float)(MM - g_nz[b]);

            for (int t0 = s_lo + g * TT; t0 < s_hi; t0 += G * TT) {
                int nT = min(TT, s_hi - t0);
                float sx[TT], sy[TT], s[TT];
#pragma unroll
                for (int t = 0; t < TT; t++) {
                    if (t < nT) { float4 sl = g_spk[sbase + t0 + t]; sx[t] = sl.x; sy[t] = sl.y; }
                    else        { sx[t] = -1e30f; sy[t] = -1e30f; }
                    s[t] = 0.f;
                }
                for (int yy = cy0; yy <= cy1; yy++) {
                    int beg = g_t_cstart[b][yy * GG + cx0];
                    int end = g_t_cstart[b][yy * GG + cx1 + 1];
                    int j0b = beg + wid * 32;
                    if (j0b >= end) continue;
                    int j = j0b + lane;
                    float4 c = (j < end) ? g_tpk[tbase + j] : PADC;
                    for (int j0 = j0b; j0 < end; j0 += OW * 32) {
                        int jn = j0 + OW * 32 + lane;
                        float4 nx = (jn < end) ? g_tpk[tbase + jn] : PADC;
#pragma unroll
                        for (int t = 0; t < TT; t++) {
                            float dx = c.x - sx[t], dy = c.y - sy[t];
                            float d2 = __fadd_rn(__fmul_rn(dx, dx), __fmul_rn(dy, dy));
                            float e = __expf(__fmul_rn(d2, NEG_INV_SCALE) + c.z);
                            s[t] += (d2 < THR2) ? e : 0.f;
                        }
                        c = nx;
                    }
                }
#pragma unroll
                for (int t = 0; t < TT; t++) {
                    float tot = s[t];
                    for (int o = 16; o; o >>= 1) tot += __shfl_xor_sync(0xffffffffu, tot, o);
                    if (lane == 0) s_red[wid][t] = tot;
                }
                __syncthreads();
                if (tid < TT) {
                    float tot = s_red[0][tid] + s_red[1][tid] + s_red[2][tid] + s_red[3][tid];
                    if (tid < nT) {
                        float st = tot + c0;
                        g_spk[sbase + t0 + tid].z = (st > 0.f) ? -__logf(st) : 1e9f;
                    }
                }
                __syncthreads();
            }
        }
        if (it < 2) gbar(&sense);
    }
}

// ===================== kernel B: output gather (f32x2 FMA) ================
__global__ __launch_bounds__(128) void k_out(const float* __restrict__ feats,
                                             float* __restrict__ out) {
    __shared__ int  s_fi[OW][32];
    __shared__ u64  s_w2[OW][32][TT];        // packed (w,w) per survivor
    __shared__ u64  red8[OW * TT * 64];      // 16KB block-reduce staging
    const float4 PADC = make_float4(1e30f, 1e30f, 0.f, 0.f);

    int tid = threadIdx.x, wid = tid >> 5, lane = tid & 31;
    int task = blockIdx.x;
    int g    = task % G;
    int cell = (task / G) % NCELL;
    int b    = task / (G * NCELL);
    int t_lo = g_t_cstart[b][cell], t_hi = g_t_cstart[b][cell + 1];
    if (t_lo + g * TT >= t_hi) return;
    int cx = cell % GG, cy = cell / GG;
    int cx0 = max(cx - 2, 0), cx1 = min(cx + 2, GG - 1);
    int cy0 = max(cy - 2, 0), cy1 = min(cy + 2, GG - 1);
    int tbase = b * MM, sbase = b * NN;
    // feature row = 128 floats = 32 ulonglong2
    const ulonglong2* f8 = (const ulonglong2*)feats + (size_t)b * NN * 32;

    for (int t0 = t_lo + g * TT; t0 < t_hi; t0 += G * TT) {
        int nT = min(TT, t_hi - t0);
        float tx[TT], ty[TT], tu[TT];
        int tidx[TT];
        u64 accxy[TT], acczw[TT];
#pragma unroll
        for (int t = 0; t < TT; t++) {
            if (t < nT) {
                float4 tl = g_tpk[tbase + t0 + t];
                tx[t] = tl.x; ty[t] = tl.y;
                tu[t] = tl.z;
                tidx[t] = __float_as_int(tl.w);
            } else { tx[t] = -1e30f; ty[t] = -1e30f; tu[t] = 0.f; tidx[t] = 0; }
            accxy[t] = 0ull; acczw[t] = 0ull;
        }
        for (int yy = cy0; yy <= cy1; yy++) {
            int beg = g_s_cstart[b][yy * GG + cx0];
            int end = g_s_cstart[b][yy * GG + cx1 + 1];
            int j0b = beg + wid * 32;
            if (j0b >= end) continue;
            int j = j0b + lane;
            float4 c = (j < end) ? g_spk[sbase + j] : PADC;
            for (int j0 = j0b; j0 < end; j0 += OW * 32) {
                int jn = j0 + OW * 32 + lane;
                float4 nx = (jn < end) ? g_spk[sbase + jn] : PADC;
                float wt[TT];
                bool anyv = false;
#pragma unroll
                for (int t = 0; t < TT; t++) {
                    float dx = tx[t] - c.x, dy = ty[t] - c.y;
                    float d2 = __fadd_rn(__fmul_rn(dx, dx), __fmul_rn(dy, dy));
                    bool val = d2 < THR2;
                    wt[t] = val ? __expf(__fmul_rn(d2, NEG_INV_SCALE) + tu[t] + c.z) : 0.f;
                    anyv |= val;
                }
                unsigned bal = __ballot_sync(0xffffffffu, anyv);
                if (anyv) {
                    int pos = __popc(bal & ((1u << lane) - 1u));
                    s_fi[wid][pos] = __float_as_int(c.w);
#pragma unroll
                    for (int t = 0; t < TT; t++) s_w2[wid][pos][t] = pack2(wt[t], wt[t]);
                }
                __syncwarp();
                int ns = __popc(bal);
                int e = 0;
                for (; e + 4 <= ns; e += 4) {
                    int fj0 = s_fi[wid][e],     fj1 = s_fi[wid][e + 1];
                    int fj2 = s_fi[wid][e + 2], fj3 = s_fi[wid][e + 3];
                    ulonglong2 A0 = f8[(size_t)fj0 * 32 + lane];
                    ulonglong2 A1 = f8[(size_t)fj1 * 32 + lane];
                    ulonglong2 A2 = f8[(size_t)fj2 * 32 + lane];
                    ulonglong2 A3 = f8[(size_t)fj3 * 32 + lane];
#pragma unroll
                    for (int t = 0; t < TT; t++) {
                        u64 w0 = s_w2[wid][e][t],     w1 = s_w2[wid][e + 1][t];
                        u64 w2 = s_w2[wid][e + 2][t], w3 = s_w2[wid][e + 3][t];
                        accxy[t] = fma2(A0.x, w0, accxy[t]); acczw[t] = fma2(A0.y, w0, acczw[t]);
                        accxy[t] = fma2(A1.x, w1, accxy[t]); acczw[t] = fma2(A1.y, w1, acczw[t]);
                        accxy[t] = fma2(A2.x, w2, accxy[t]); acczw[t] = fma2(A2.y, w2, acczw[t]);
                        accxy[t] = fma2(A3.x, w3, accxy[t]); acczw[t] = fma2(A3.y, w3, acczw[t]);
                    }
                }
                for (; e < ns; e++) {
                    int fj = s_fi[wid][e];
                    ulonglong2 A = f8[(size_t)fj * 32 + lane];
#pragma unroll
                    for (int t = 0; t < TT; t++) {
                        u64 w = s_w2[wid][e][t];
                        accxy[t] = fma2(A.x, w, accxy[t]);
                        acczw[t] = fma2(A.y, w, acczw[t]);
                    }
                }
                __syncwarp();
                c = nx;
            }
        }
        // block reduce partials -> out
#pragma unroll
        for (int t = 0; t < TT; t++) {
            red8[(wid * TT + t) * 64 + lane * 2]     = accxy[t];
            red8[(wid * TT + t) * 64 + lane * 2 + 1] = acczw[t];
        }
        __syncthreads();
        for (int t = wid; t < nT; t += OW) {
            u64 x0 = red8[(0 * TT + t) * 64 + lane * 2];
            u64 x1 = red8[(1 * TT + t) * 64 + lane * 2];
            u64 x2 = red8[(2 * TT + t) * 64 + lane * 2];
            u64 x3 = red8[(3 * TT + t) * 64 + lane * 2];
            u64 z0 = red8[(0 * TT + t) * 64 + lane * 2 + 1];
            u64 z1 = red8[(1 * TT + t) * 64 + lane * 2 + 1];
            u64 z2 = red8[(2 * TT + t) * 64 + lane * 2 + 1];
            u64 z3 = red8[(3 * TT + t) * 64 + lane * 2 + 1];
            ulonglong2 r;
            r.x = add2(add2(x0, x1), add2(x2, x3));
            r.y = add2(add2(z0, z1), add2(z2, z3));
            ((ulonglong2*)out)[((size_t)tbase + tidx[t]) * 32 + lane] = r;
        }
        __syncthreads();
    }
}

// ---------------- launch ----------------
extern "C" void kernel_launch(void* const* d_in, const int* in_sizes, int n_in,
                              void* d_out, int out_size) {
    const float* feats = (const float*)d_in[0];
    const float* slocs = (const float*)d_in[1];
    const float* tlocs = (const float*)d_in[2];
    const void*  smask = d_in[3];
    const void*  tmask = d_in[4];
    float* out = (float*)d_out;

    k_solve<<<GRIDA, 128>>>(slocs, tlocs, smask, tmask, out);
    k_out<<<NTASK, 128>>>(feats, out);
}

// round 16
// speedup vs baseline: 1.4523x; 1.4523x over previous
#include <cuda_runtime.h>
#include <cstdint>
#include <cstddef>

#define BB 4
#define NN 4096
#define MM 4096
#define CC 128

#define GG 10
#define NCELL (GG*GG)

#define TT 8          // rows per task (row-group)
#define OW 4          // warps per block
#define G  8          // row-group slots per cell (finer tasks: tail shrink)
#define NTASK (BB*NCELL*G)   // 3200
#define GRID 888      // 6 blocks/SM * 148 SMs — full residency guaranteed

#define THR2 0.04f
#define NEG_INV_SCALE (-99.9999000001f)   /* -(1/(0.01+1e-8)) */

// ---------------- scratch (device globals; no allocation) ----------------
__device__ int    g_mask_i32;

__device__ float2 g_ss_loc[BB*NN];
__device__ int    g_ss_idx[BB*NN];
__device__ int    g_s_cstart[BB][NCELL+1];
__device__ float2 g_ts_loc[BB*MM];
__device__ int    g_ts_idx[BB*MM];
__device__ int    g_t_cstart[BB][NCELL+1];

__device__ float  g_us[BB*MM];   // u in sorted-target order
__device__ float  g_vs[BB*NN];   // v in sorted-source order
__device__ int    g_nz[BB];      // # target rows with >=1 valid pair

// work-stealing counters: [0,2,4]=u it0..2, [1,3,5]=v it0..2, [6]=out.
// Reset every launch during init phase (graph-replay safe).
__device__ int    g_ctr[7];

// barrier state: g_bar_count returns to 0 after each barrier; g_bar_sense
// flips per barrier — 8 barriers per launch (EVEN) returns it to 0.
__device__ int           g_bar_count;
__device__ volatile int  g_bar_sense;

__device__ __forceinline__ void gbar(int* sense) {
    __threadfence();
    __syncthreads();
    if (threadIdx.x == 0) {
        int s = *sense ^ 1;
        *sense = s;
        int a = atomicAdd(&g_bar_count, 1);
        if (a == GRID - 1) {
            g_bar_count = 0;
            __threadfence();
            g_bar_sense = s;
        } else {
            while (g_bar_sense != s) __nanosleep(32);
        }
    }
    __syncthreads();
    __threadfence();
}

__device__ __forceinline__ bool mask_at(const void* p, int i) {
    return g_mask_i32 ? (((const int*)p)[i] != 0)
                      : (((const unsigned char*)p)[i] != 0);
}

__device__ __forceinline__ int cell_of(float2 p) {
    int cx = (int)(p.x * GG); cx = min(max(cx, 0), GG - 1);
    int cy = (int)(p.y * GG); cy = min(max(cy, 0), GG - 1);
    return cy * GG + cx;
}

// shared memory overlay: sort phase vs output phase
struct SmemSort {
    int hist[4][NCELL];
    int cst[NCELL + 1];
};
struct SmemOut {
    int    fi[OW][32];
    float  w[OW][32][9];        // 8 weights padded to 9
    float4 red4[OW * TT * 32];  // 16KB block-reduce staging
};
union SmemU {
    SmemSort sort;
    SmemOut  outp;
};

__global__ __launch_bounds__(128, 6) void k_fused(
    const float* __restrict__ feats,
    const float* __restrict__ slocs,
    const float* __restrict__ tlocs,
    const void*  __restrict__ smask,
    const void*  __restrict__ tmask,
    float* __restrict__ out)
{
    __shared__ SmemU sm;
    __shared__ float s_red[OW][TT];
    __shared__ int s_flag;
    __shared__ int s_task;

    int tid = threadIdx.x, wid = tid >> 5, lane = tid & 31;
    int blk = blockIdx.x;
    int sense = 0;

    // ================= phase 0: init (detect dtype, zero state/out) ======
    if (blk == 0) {
        if (tid == 0) s_flag = 0;
        __syncthreads();
        int acc = 0;
        const unsigned char* smb = (const unsigned char*)smask;
        for (int p = tid; p < 16384; p += 128)
            if (p & 3) acc |= smb[p];
        if (acc) atomicOr(&s_flag, 1);
        __syncthreads();
        if (tid == 0) g_mask_i32 = (s_flag == 0);
    } else {
        int gt = (blk - 1) * 128 + tid, nt = (GRID - 1) * 128;
        for (int i = gt; i < BB * NN; i += nt) g_vs[i] = 0.f;
        float4* o4 = (float4*)out;
        for (int i = gt; i < BB * MM * (CC / 4); i += nt)
            o4[i] = make_float4(0.f, 0.f, 0.f, 0.f);
        if (gt < BB) g_nz[gt] = 0;
        if (blk == 8 && tid < 7) g_ctr[tid] = 0;
    }
    gbar(&sense);   // barrier 1

    // ================= phase 1: sort (blocks 0..7) ========================
    if (blk < 8) {
        int which = blk >> 2, b = blk & 3;
        const void*   mk   = which ? tmask : smask;
        const float2* loc  = (const float2*)(which ? tlocs : slocs);
        float2*       oloc = which ? g_ts_loc : g_ss_loc;
        int*          oidx = which ? g_ts_idx : g_ss_idx;
        int*          cst  = which ? g_t_cstart[b] : g_s_cstart[b];
        int base = b * NN;

        for (int c = tid; c < 4 * NCELL; c += 128) ((int*)sm.sort.hist)[c] = 0;
        __syncthreads();

        int i0w = wid * 1024;
        for (int i0 = i0w; i0 < i0w + 1024; i0 += 32) {
            int i = i0 + lane;
            if (mask_at(mk, base + i))
                atomicAdd(&sm.sort.hist[wid][cell_of(loc[base + i])], 1);
        }
        __syncthreads();

        if (tid == 0) {
            int run = 0;
            for (int c = 0; c < NCELL; c++) {
                sm.sort.cst[c] = run;
                int t = 0;
                for (int ww = 0; ww < 4; ww++) t += sm.sort.hist[ww][c];
                run += t;
            }
            sm.sort.cst[NCELL] = run;
            for (int c = 0; c <= NCELL; c++) cst[c] = sm.sort.cst[c];
        }
        __syncthreads();

        if (tid < NCELL) {
            int run = sm.sort.cst[tid];
            for (int ww = 0; ww < 4; ww++) {
                int h = sm.sort.hist[ww][tid];
                sm.sort.hist[ww][tid] = run;
                run += h;
            }
        }
        __syncthreads();

        for (int i0 = i0w; i0 < i0w + 1024; i0 += 32) {
            int i = i0 + lane;
            bool m = mask_at(mk, base + i);
            float2 p = m ? loc[base + i] : make_float2(0.f, 0.f);
            int cell = m ? cell_of(p) : (1000 + lane);
            unsigned peers = __match_any_sync(0xffffffffu, cell);
            if (m) {
                int leader = __ffs(peers) - 1;
                int rank = __popc(peers & ((1u << lane) - 1u));
                int bse = 0;
                if (lane == leader) bse = sm.sort.hist[wid][cell];
                bse = __shfl_sync(peers, bse, leader);
                int pos = base + bse + rank;
                oloc[pos] = p;
                oidx[pos] = i;
                if (lane == leader) sm.sort.hist[wid][cell] = bse + __popc(peers);
            }
        }
    }
    gbar(&sense);   // barrier 2

    // ================= 3 Sinkhorn iterations ==============================
    for (int it = 0; it < 3; it++) {
        // ---- u update (work-stealing on g_ctr[it*2]) ----
        for (;;) {
            __syncthreads();
            if (tid == 0) s_task = atomicAdd(&g_ctr[it * 2], 1);
            __syncthreads();
            int task = s_task;
            if (task >= NTASK) break;
            int g    = task % G;
            int cell = (task / G) % NCELL;
            int b    = task / (G * NCELL);
            int t_lo = g_t_cstart[b][cell], t_hi = g_t_cstart[b][cell + 1];
            if (t_lo + g * TT >= t_hi) continue;
            int cx = cell % GG, cy = cell / GG;
            int cx0 = max(cx - 2, 0), cx1 = min(cx + 2, GG - 1);
            int cy0 = max(cy - 2, 0), cy1 = min(cy + 2, GG - 1);
            int tbase = b * MM, sbase = b * NN;

            for (int t0 = t_lo + g * TT; t0 < t_hi; t0 += G * TT) {
                int nT = min(TT, t_hi - t0);
                float tx[TT], ty[TT], s[TT];
#pragma unroll
                for (int t = 0; t < TT; t++) {
                    if (t < nT) { float2 tl = g_ts_loc[tbase + t0 + t]; tx[t] = tl.x; ty[t] = tl.y; }
                    else        { tx[t] = -1e30f; ty[t] = -1e30f; }
                    s[t] = 0.f;
                }
                for (int yy = cy0; yy <= cy1; yy++) {
                    int beg = g_s_cstart[b][yy * GG + cx0];
                    int end = g_s_cstart[b][yy * GG + cx1 + 1];
                    for (int j0 = beg + wid * 32; j0 < end; j0 += OW * 32) {
                        int j = j0 + lane;
                        bool pr = j < end;
                        float2 sl = pr ? g_ss_loc[sbase + j] : make_float2(1e30f, 1e30f);
                        float vv  = pr ? g_vs[sbase + j] : 0.f;
#pragma unroll
                        for (int t = 0; t < TT; t++) {
                            float dx = tx[t] - sl.x, dy = ty[t] - sl.y;
                            float d2 = __fadd_rn(__fmul_rn(dx, dx), __fmul_rn(dy, dy));
                            if (d2 < THR2) s[t] += __expf(__fmul_rn(d2, NEG_INV_SCALE) + vv);
                        }
                    }
                }
#pragma unroll
                for (int t = 0; t < TT; t++) {
                    float tot = s[t];
                    for (int o = 16; o; o >>= 1) tot += __shfl_xor_sync(0xffffffffu, tot, o);
                    if (lane == 0) s_red[wid][t] = tot;
                }
                __syncthreads();
                if (tid < TT) {
                    float tot = s_red[0][tid] + s_red[1][tid] + s_red[2][tid] + s_red[3][tid];
                    if (tid < nT) {
                        g_us[tbase + t0 + tid] = (tot > 0.f) ? -__logf(tot) : 1e9f;
                        if (it == 0 && tot > 0.f) atomicAdd(&g_nz[b], 1);
                    }
                }
                __syncthreads();
            }
        }
        gbar(&sense);   // barriers 3,5,7

        // ---- v update (work-stealing on g_ctr[it*2+1]) ----
        for (;;) {
            __syncthreads();
            if (tid == 0) s_task = atomicAdd(&g_ctr[it * 2 + 1], 1);
            __syncthreads();
            int task = s_task;
            if (task >= NTASK) break;
            int g    = task % G;
            int cell = (task / G) % NCELL;
            int b    = task / (G * NCELL);
            int s_lo = g_s_cstart[b][cell], s_hi = g_s_cstart[b][cell + 1];
            if (s_lo + g * TT >= s_hi) continue;
            int cx = cell % GG, cy = cell / GG;
            int cx0 = max(cx - 2, 0), cx1 = min(cx + 2, GG - 1);
            int cy0 = max(cy - 2, 0), cy1 = min(cy + 2, GG - 1);
            int tbase = b * MM, sbase = b * NN;
            float c0 = (float)(MM - g_nz[b]);

            for (int t0 = s_lo + g * TT; t0 < s_hi; t0 += G * TT) {
                int nT = min(TT, s_hi - t0);
                float sx[TT], sy[TT], s[TT];
#pragma unroll
                for (int t = 0; t < TT; t++) {
                    if (t < nT) { float2 sl = g_ss_loc[sbase + t0 + t]; sx[t] = sl.x; sy[t] = sl.y; }
                    else        { sx[t] = -1e30f; sy[t] = -1e30f; }
                    s[t] = 0.f;
                }
                for (int yy = cy0; yy <= cy1; yy++) {
                    int beg = g_t_cstart[b][yy * GG + cx0];
                    int end = g_t_cstart[b][yy * GG + cx1 + 1];
                    for (int j0 = beg + wid * 32; j0 < end; j0 += OW * 32) {
                        int j = j0 + lane;
                        bool pr = j < end;
                        float2 tl = pr ? g_ts_loc[tbase + j] : make_float2(1e30f, 1e30f);
                        float uu  = pr ? g_us[tbase + j] : 0.f;
#pragma unroll
                        for (int t = 0; t < TT; t++) {
                            float dx = tl.x - sx[t], dy = tl.y - sy[t];
                            float d2 = __fadd_rn(__fmul_rn(dx, dx), __fmul_rn(dy, dy));
                            if (d2 < THR2) s[t] += __expf(__fmul_rn(d2, NEG_INV_SCALE) + uu);
                        }
                    }
                }
#pragma unroll
                for (int t = 0; t < TT; t++) {
                    float tot = s[t];
                    for (int o = 16; o; o >>= 1) tot += __shfl_xor_sync(0xffffffffu, tot, o);
                    if (lane == 0) s_red[wid][t] = tot;
                }
                __syncthreads();
                if (tid < TT) {
                    float tot = s_red[0][tid] + s_red[1][tid] + s_red[2][tid] + s_red[3][tid];
                    if (tid < nT) {
                        float st = tot + c0;
                        g_vs[sbase + t0 + tid] = (st > 0.f) ? -__logf(st) : 1e9f;
                    }
                }
                __syncthreads();
            }
        }
        gbar(&sense);   // barriers 4,6,8
    }

    // ================= phase out (work-stealing on g_ctr[6]) ==============
    const float4* f4base = (const float4*)feats;
    for (;;) {
        __syncthreads();
        if (tid == 0) s_task = atomicAdd(&g_ctr[6], 1);
        __syncthreads();
        int task = s_task;
        if (task >= NTASK) break;
        int g    = task % G;
        int cell = (task / G) % NCELL;
        int b    = task / (G * NCELL);
        int t_lo = g_t_cstart[b][cell], t_hi = g_t_cstart[b][cell + 1];
        if (t_lo + g * TT >= t_hi) continue;
        int cx = cell % GG, cy = cell / GG;
        int cx0 = max(cx - 2, 0), cx1 = min(cx + 2, GG - 1);
        int cy0 = max(cy - 2, 0), cy1 = min(cy + 2, GG - 1);
        int tbase = b * MM, sbase = b * NN;
        const float4* f4 = f4base + (size_t)b * NN * (CC / 4);

        for (int t0 = t_lo + g * TT; t0 < t_hi; t0 += G * TT) {
            int nT = min(TT, t_hi - t0);
            float tx[TT], ty[TT], tu[TT];
            int tidx[TT];
            float4 acc[TT];
#pragma unroll
            for (int t = 0; t < TT; t++) {
                if (t < nT) {
                    float2 tl = g_ts_loc[tbase + t0 + t];
                    tx[t] = tl.x; ty[t] = tl.y;
                    tu[t] = g_us[tbase + t0 + t];
                    tidx[t] = g_ts_idx[tbase + t0 + t];
                } else { tx[t] = -1e30f; ty[t] = -1e30f; tu[t] = 0.f; tidx[t] = 0; }
                acc[t] = make_float4(0.f, 0.f, 0.f, 0.f);
            }
            for (int yy = cy0; yy <= cy1; yy++) {
                int beg = g_s_cstart[b][yy * GG + cx0];
                int end = g_s_cstart[b][yy * GG + cx1 + 1];
                for (int j0 = beg + wid * 32; j0 < end; j0 += OW * 32) {
                    int j = j0 + lane;
                    bool pr = j < end;
                    float2 sl = pr ? g_ss_loc[sbase + j] : make_float2(1e30f, 1e30f);
                    float vv  = pr ? g_vs[sbase + j] : 0.f;
                    int fidx  = pr ? g_ss_idx[sbase + j] : 0;
                    float wt[TT];
                    bool anyv = false;
#pragma unroll
                    for (int t = 0; t < TT; t++) {
                        float dx = tx[t] - sl.x, dy = ty[t] - sl.y;
                        float d2 = __fadd_rn(__fmul_rn(dx, dx), __fmul_rn(dy, dy));
                        bool val = d2 < THR2;
                        wt[t] = val ? __expf(__fmul_rn(d2, NEG_INV_SCALE) + tu[t] + vv) : 0.f;
                        anyv |= val;
                    }
                    unsigned bal = __ballot_sync(0xffffffffu, anyv);
                    if (anyv) {
                        int pos = __popc(bal & ((1u << lane) - 1u));
                        sm.outp.fi[wid][pos] = fidx;
#pragma unroll
                        for (int t = 0; t < TT; t++) sm.outp.w[wid][pos][t] = wt[t];
                    }
                    __syncwarp();
                    int ns = __popc(bal);
                    int e = 0;
                    for (; e + 4 <= ns; e += 4) {
                        int fj0 = sm.outp.fi[wid][e],     fj1 = sm.outp.fi[wid][e + 1];
                        int fj2 = sm.outp.fi[wid][e + 2], fj3 = sm.outp.fi[wid][e + 3];
                        float4 a0 = f4[(size_t)fj0 * (CC / 4) + lane];
                        float4 a1 = f4[(size_t)fj1 * (CC / 4) + lane];
                        float4 a2 = f4[(size_t)fj2 * (CC / 4) + lane];
                        float4 a3 = f4[(size_t)fj3 * (CC / 4) + lane];
#pragma unroll
                        for (int t = 0; t < TT; t++) {
                            float w0 = sm.outp.w[wid][e][t],     w1 = sm.outp.w[wid][e + 1][t];
                            float w2 = sm.outp.w[wid][e + 2][t], w3 = sm.outp.w[wid][e + 3][t];
                            acc[t].x = fmaf(w0, a0.x, acc[t].x); acc[t].y = fmaf(w0, a0.y, acc[t].y);
                            acc[t].z = fmaf(w0, a0.z, acc[t].z); acc[t].w = fmaf(w0, a0.w, acc[t].w);
                            acc[t].x = fmaf(w1, a1.x, acc[t].x); acc[t].y = fmaf(w1, a1.y, acc[t].y);
                            acc[t].z = fmaf(w1, a1.z, acc[t].z); acc[t].w = fmaf(w1, a1.w, acc[t].w);
                            acc[t].x = fmaf(w2, a2.x, acc[t].x); acc[t].y = fmaf(w2, a2.y, acc[t].y);
                            acc[t].z = fmaf(w2, a2.z, acc[t].z); acc[t].w = fmaf(w2, a2.w, acc[t].w);
                            acc[t].x = fmaf(w3, a3.x, acc[t].x); acc[t].y = fmaf(w3, a3.y, acc[t].y);
                            acc[t].z = fmaf(w3, a3.z, acc[t].z); acc[t].w = fmaf(w3, a3.w, acc[t].w);
                        }
                    }
                    for (; e < ns; e++) {
                        int fj = sm.outp.fi[wid][e];
                        float4 a = f4[(size_t)fj * (CC / 4) + lane];
#pragma unroll
                        for (int t = 0; t < TT; t++) {
                            float w = sm.outp.w[wid][e][t];
                            acc[t].x = fmaf(w, a.x, acc[t].x); acc[t].y = fmaf(w, a.y, acc[t].y);
                            acc[t].z = fmaf(w, a.z, acc[t].z); acc[t].w = fmaf(w, a.w, acc[t].w);
                        }
                    }
                    __syncwarp();
                }
            }
            // block reduce partials -> out
#pragma unroll
            for (int t = 0; t < TT; t++)
                sm.outp.red4[(wid * TT + t) * 32 + lane] = acc[t];
            __syncthreads();
            for (int t = wid; t < nT; t += OW) {
                float4 a0 = sm.outp.red4[(0 * TT + t) * 32 + lane];
                float4 a1 = sm.outp.red4[(1 * TT + t) * 32 + lane];
                float4 a2 = sm.outp.red4[(2 * TT + t) * 32 + lane];
                float4 a3 = sm.outp.red4[(3 * TT + t) * 32 + lane];
                float4 r;
                r.x = (a0.x + a1.x) + (a2.x + a3.x);
                r.y = (a0.y + a1.y) + (a2.y + a3.y);
                r.z = (a0.z + a1.z) + (a2.z + a3.z);
                r.w = (a0.w + a1.w) + (a2.w + a3.w);
                ((float4*)out)[((size_t)tbase + tidx[t]) * (CC / 4) + lane] = r;
            }
            __syncthreads();
        }
    }
}

// ---------------- launch ----------------
extern "C" void kernel_launch(void* const* d_in, const int* in_sizes, int n_in,
                              void* d_out, int out_size) {
    const float* feats = (const float*)d_in[0];
    const float* slocs = (const float*)d_in[1];
    const float* tlocs = (const float*)d_in[2];
    const void*  smask = d_in[3];
    const void*  tmask = d_in[4];
    float* out = (float*)d_out;

    k_fused<<<GRID, 128>>>(feats, slocs, tlocs, smask, tmask, out);
}

// round 17
// speedup vs baseline: 1.5742x; 1.0840x over previous
#include <cuda_runtime.h>
#include <cstdint>
#include <cstddef>

#define BB 4
#define NN 4096
#define MM 4096
#define CC 128

#define GG 10
#define NCELL (GG*GG)

#define TT 8          // rows per task (row-group)
#define OW 4          // warps per block
#define G  8          // row-group slots per cell
#define NTASKB (NCELL*G)     // 800 tasks per batch
#define GRID 888             // 6 blocks/SM * 148 SMs — residency guaranteed
#define NB (GRID/4)          // 222 blocks per batch

#define THR2 0.04f
#define NEG_INV_SCALE (-99.9999000001f)   /* -(1/(0.01+1e-8)) */

// ---------------- scratch (device globals; no allocation) ----------------
__device__ int    g_mask[4];          // per-batch mask-dtype flag (identical values)

__device__ float2 g_ss_loc[BB*NN];
__device__ int    g_ss_idx[BB*NN];
__device__ int    g_s_cstart[BB][NCELL+1];
__device__ float2 g_ts_loc[BB*MM];
__device__ int    g_ts_idx[BB*MM];
__device__ int    g_t_cstart[BB][NCELL+1];

__device__ float  g_us[BB*MM];   // u in sorted-target order
__device__ float  g_vs[BB*NN];   // v in sorted-source order
__device__ int    g_nz[BB];      // # target rows with >=1 valid pair

// per-batch work-stealing counters: [b][0,2,4]=u, [b][1,3,5]=v, [b][6]=out
__device__ int    g_ctrB[4][8];

// per-batch barrier state, padded to distinct cache lines.
// Sense is READ at kernel entry -> replay-safe for any barrier count.
__device__ int           g_bcnt[4*32];
__device__ volatile int  g_bsense[4*32];

__device__ __forceinline__ void gbar_b(int b, int* sense) {
    __threadfence();
    __syncthreads();
    if (threadIdx.x == 0) {
        int s = *sense ^ 1;
        *sense = s;
        int a = atomicAdd(&g_bcnt[b * 32], 1);
        if (a == NB - 1) {
            g_bcnt[b * 32] = 0;
            __threadfence();
            g_bsense[b * 32] = s;
        } else {
            while (g_bsense[b * 32] != s) __nanosleep(32);
        }
    }
    __syncthreads();
    __threadfence();
}

__device__ __forceinline__ bool mask_at(int m32, const void* p, int i) {
    return m32 ? (((const int*)p)[i] != 0)
               : (((const unsigned char*)p)[i] != 0);
}

__device__ __forceinline__ int cell_of(float2 p) {
    int cx = (int)(p.x * GG); cx = min(max(cx, 0), GG - 1);
    int cy = (int)(p.y * GG); cy = min(max(cy, 0), GG - 1);
    return cy * GG + cx;
}

// shared memory overlay: sort phase vs output phase
struct SmemSort {
    int hist[4][NCELL];
    int cst[NCELL + 1];
};
struct SmemOut {
    int    fi[OW][32];
    float  w[OW][32][9];        // 8 weights padded to 9
    float4 red4[OW * TT * 32];  // 16KB block-reduce staging
};
union SmemU {
    SmemSort sort;
    SmemOut  outp;
};

__global__ __launch_bounds__(128, 6) void k_fused(
    const float* __restrict__ feats,
    const float* __restrict__ slocs,
    const float* __restrict__ tlocs,
    const void*  __restrict__ smask,
    const void*  __restrict__ tmask,
    float* __restrict__ out)
{
    __shared__ SmemU sm;
    __shared__ float s_red[OW][TT];
    __shared__ int s_flag;
    __shared__ int s_task;
    __shared__ int s_sense0;

    int tid = threadIdx.x, wid = tid >> 5, lane = tid & 31;
    int blk = blockIdx.x;
    int b    = blk & 3;        // batch
    int bblk = blk >> 2;       // block index within batch (0..221)

    if (tid == 0) s_sense0 = g_bsense[b * 32];
    __syncthreads();
    int sense = s_sense0;

    // ======= phase 0: init (per batch: detect dtype, reset, zero) ========
    if (bblk == 0) {
        if (tid == 0) s_flag = 0;
        __syncthreads();
        int acc = 0;
        const unsigned char* smb = (const unsigned char*)smask;
        for (int p = tid; p < 16384; p += 128)
            if (p & 3) acc |= smb[p];
        if (acc) atomicOr(&s_flag, 1);
        __syncthreads();
        if (tid == 0) { g_mask[b] = (s_flag == 0); g_nz[b] = 0; }
        if (tid < 8) g_ctrB[b][tid] = 0;
    } else {
        int gt = (bblk - 1) * 128 + tid, nt = (NB - 1) * 128;
        for (int i = gt; i < NN; i += nt) g_vs[b * NN + i] = 0.f;
        float4* o4 = (float4*)out + (size_t)b * MM * (CC / 4);
        for (int i = gt; i < MM * (CC / 4); i += nt)
            o4[i] = make_float4(0.f, 0.f, 0.f, 0.f);
    }
    gbar_b(b, &sense);   // barrier 1

    int m32 = g_mask[b];

    // ============== phase 1: sort (2 blocks per batch) ====================
    if (bblk < 2) {
        int which = bblk;
        const void*   mk   = which ? tmask : smask;
        const float2* loc  = (const float2*)(which ? tlocs : slocs);
        float2*       oloc = which ? g_ts_loc : g_ss_loc;
        int*          oidx = which ? g_ts_idx : g_ss_idx;
        int*          cst  = which ? g_t_cstart[b] : g_s_cstart[b];
        int base = b * NN;

        for (int c = tid; c < 4 * NCELL; c += 128) ((int*)sm.sort.hist)[c] = 0;
        __syncthreads();

        int i0w = wid * 1024;
        for (int i0 = i0w; i0 < i0w + 1024; i0 += 32) {
            int i = i0 + lane;
            if (mask_at(m32, mk, base + i))
                atomicAdd(&sm.sort.hist[wid][cell_of(loc[base + i])], 1);
        }
        __syncthreads();

        if (tid == 0) {
            int run = 0;
            for (int c = 0; c < NCELL; c++) {
                sm.sort.cst[c] = run;
                int t = 0;
                for (int ww = 0; ww < 4; ww++) t += sm.sort.hist[ww][c];
                run += t;
            }
            sm.sort.cst[NCELL] = run;
            for (int c = 0; c <= NCELL; c++) cst[c] = sm.sort.cst[c];
        }
        __syncthreads();

        if (tid < NCELL) {
            int run = sm.sort.cst[tid];
            for (int ww = 0; ww < 4; ww++) {
                int h = sm.sort.hist[ww][tid];
                sm.sort.hist[ww][tid] = run;
                run += h;
            }
        }
        __syncthreads();

        for (int i0 = i0w; i0 < i0w + 1024; i0 += 32) {
            int i = i0 + lane;
            bool m = mask_at(m32, mk, base + i);
            float2 p = m ? loc[base + i] : make_float2(0.f, 0.f);
            int cell = m ? cell_of(p) : (1000 + lane);
            unsigned peers = __match_any_sync(0xffffffffu, cell);
            if (m) {
                int leader = __ffs(peers) - 1;
                int rank = __popc(peers & ((1u << lane) - 1u));
                int bse = 0;
                if (lane == leader) bse = sm.sort.hist[wid][cell];
                bse = __shfl_sync(peers, bse, leader);
                int pos = base + bse + rank;
                oloc[pos] = p;
                oidx[pos] = i;
                if (lane == leader) sm.sort.hist[wid][cell] = bse + __popc(peers);
            }
        }
    }
    gbar_b(b, &sense);   // barrier 2

    // ================= 3 Sinkhorn iterations (per batch) ==================
    for (int it = 0; it < 3; it++) {
        // ---- u update (stealing on g_ctrB[b][it*2]) ----
        for (;;) {
            __syncthreads();
            if (tid == 0) s_task = atomicAdd(&g_ctrB[b][it * 2], 1);
            __syncthreads();
            int task = s_task;
            if (task >= NTASKB) break;
            int g    = task % G;
            int cell = task / G;
            int t_lo = g_t_cstart[b][cell], t_hi = g_t_cstart[b][cell + 1];
            if (t_lo + g * TT >= t_hi) continue;
            int cx = cell % GG, cy = cell / GG;
            int cx0 = max(cx - 2, 0), cx1 = min(cx + 2, GG - 1);
            int cy0 = max(cy - 2, 0), cy1 = min(cy + 2, GG - 1);
            int tbase = b * MM, sbase = b * NN;

            for (int t0 = t_lo + g * TT; t0 < t_hi; t0 += G * TT) {
                int nT = min(TT, t_hi - t0);
                float tx[TT], ty[TT], s[TT];
#pragma unroll
                for (int t = 0; t < TT; t++) {
                    if (t < nT) { float2 tl = g_ts_loc[tbase + t0 + t]; tx[t] = tl.x; ty[t] = tl.y; }
                    else        { tx[t] = -1e30f; ty[t] = -1e30f; }
                    s[t] = 0.f;
                }
                for (int yy = cy0; yy <= cy1; yy++) {
                    int beg = g_s_cstart[b][yy * GG + cx0];
                    int end = g_s_cstart[b][yy * GG + cx1 + 1];
                    for (int j0 = beg + wid * 32; j0 < end; j0 += OW * 32) {
                        int j = j0 + lane;
                        bool pr = j < end;
                        float2 sl = pr ? g_ss_loc[sbase + j] : make_float2(1e30f, 1e30f);
                        float vv  = pr ? g_vs[sbase + j] : 0.f;
#pragma unroll
                        for (int t = 0; t < TT; t++) {
                            float dx = tx[t] - sl.x, dy = ty[t] - sl.y;
                            float d2 = __fadd_rn(__fmul_rn(dx, dx), __fmul_rn(dy, dy));
                            if (d2 < THR2) s[t] += __expf(__fmul_rn(d2, NEG_INV_SCALE) + vv);
                        }
                    }
                }
#pragma unroll
                for (int t = 0; t < TT; t++) {
                    float tot = s[t];
                    for (int o = 16; o; o >>= 1) tot += __shfl_xor_sync(0xffffffffu, tot, o);
                    if (lane == 0) s_red[wid][t] = tot;
                }
                __syncthreads();
                if (tid < TT) {
                    float tot = s_red[0][tid] + s_red[1][tid] + s_red[2][tid] + s_red[3][tid];
                    if (tid < nT) {
                        g_us[tbase + t0 + tid] = (tot > 0.f) ? -__logf(tot) : 1e9f;
                        if (it == 0 && tot > 0.f) atomicAdd(&g_nz[b], 1);
                    }
                }
                __syncthreads();
            }
        }
        gbar_b(b, &sense);   // barriers 3,5,7

        // ---- v update (stealing on g_ctrB[b][it*2+1]) ----
        for (;;) {
            __syncthreads();
            if (tid == 0) s_task = atomicAdd(&g_ctrB[b][it * 2 + 1], 1);
            __syncthreads();
            int task = s_task;
            if (task >= NTASKB) break;
            int g    = task % G;
            int cell = task / G;
            int s_lo = g_s_cstart[b][cell], s_hi = g_s_cstart[b][cell + 1];
            if (s_lo + g * TT >= s_hi) continue;
            int cx = cell % GG, cy = cell / GG;
            int cx0 = max(cx - 2, 0), cx1 = min(cx + 2, GG - 1);
            int cy0 = max(cy - 2, 0), cy1 = min(cy + 2, GG - 1);
            int tbase = b * MM, sbase = b * NN;
            float c0 = (float)(MM - g_nz[b]);

            for (int t0 = s_lo + g * TT; t0 < s_hi; t0 += G * TT) {
                int nT = min(TT, s_hi - t0);
                float sx[TT], sy[TT], s[TT];
#pragma unroll
                for (int t = 0; t < TT; t++) {
                    if (t < nT) { float2 sl = g_ss_loc[sbase + t0 + t]; sx[t] = sl.x; sy[t] = sl.y; }
                    else        { sx[t] = -1e30f; sy[t] = -1e30f; }
                    s[t] = 0.f;
                }
                for (int yy = cy0; yy <= cy1; yy++) {
                    int beg = g_t_cstart[b][yy * GG + cx0];
                    int end = g_t_cstart[b][yy * GG + cx1 + 1];
                    for (int j0 = beg + wid * 32; j0 < end; j0 += OW * 32) {
                        int j = j0 + lane;
                        bool pr = j < end;
                        float2 tl = pr ? g_ts_loc[tbase + j] : make_float2(1e30f, 1e30f);
                        float uu  = pr ? g_us[tbase + j] : 0.f;
#pragma unroll
                        for (int t = 0; t < TT; t++) {
                            float dx = tl.x - sx[t], dy = tl.y - sy[t];
                            float d2 = __fadd_rn(__fmul_rn(dx, dx), __fmul_rn(dy, dy));
                            if (d2 < THR2) s[t] += __expf(__fmul_rn(d2, NEG_INV_SCALE) + uu);
                        }
                    }
                }
#pragma unroll
                for (int t = 0; t < TT; t++) {
                    float tot = s[t];
                    for (int o = 16; o; o >>= 1) tot += __shfl_xor_sync(0xffffffffu, tot, o);
                    if (lane == 0) s_red[wid][t] = tot;
                }
                __syncthreads();
                if (tid < TT) {
                    float tot = s_red[0][tid] + s_red[1][tid] + s_red[2][tid] + s_red[3][tid];
                    if (tid < nT) {
                        float st = tot + c0;
                        g_vs[sbase + t0 + tid] = (st > 0.f) ? -__logf(st) : 1e9f;
                    }
                }
                __syncthreads();
            }
        }
        gbar_b(b, &sense);   // barriers 4,6,8
    }

    // ===== phase out (per-batch stealing; overlaps with other batches) ====
    const float4* f4base = (const float4*)feats;
    for (;;) {
        __syncthreads();
        if (tid == 0) s_task = atomicAdd(&g_ctrB[b][6], 1);
        __syncthreads();
        int task = s_task;
        if (task >= NTASKB) break;
        int g    = task % G;
        int cell = task / G;
        int t_lo = g_t_cstart[b][cell], t_hi = g_t_cstart[b][cell + 1];
        if (t_lo + g * TT >= t_hi) continue;
        int cx = cell % GG, cy = cell / GG;
        int cx0 = max(cx - 2, 0), cx1 = min(cx + 2, GG - 1);
        int cy0 = max(cy - 2, 0), cy1 = min(cy + 2, GG - 1);
        int tbase = b * MM, sbase = b * NN;
        const float4* f4 = f4base + (size_t)b * NN * (CC / 4);

        for (int t0 = t_lo + g * TT; t0 < t_hi; t0 += G * TT) {
            int nT = min(TT, t_hi - t0);
            float tx[TT], ty[TT], tu[TT];
            int tidx[TT];
            float4 acc[TT];
#pragma unroll
            for (int t = 0; t < TT; t++) {
                if (t < nT) {
                    float2 tl = g_ts_loc[tbase + t0 + t];
                    tx[t] = tl.x; ty[t] = tl.y;
                    tu[t] = g_us[tbase + t0 + t];
                    tidx[t] = g_ts_idx[tbase + t0 + t];
                } else { tx[t] = -1e30f; ty[t] = -1e30f; tu[t] = 0.f; tidx[t] = 0; }
                acc[t] = make_float4(0.f, 0.f, 0.f, 0.f);
            }
            for (int yy = cy0; yy <= cy1; yy++) {
                int beg = g_s_cstart[b][yy * GG + cx0];
                int end = g_s_cstart[b][yy * GG + cx1 + 1];
                for (int j0 = beg + wid * 32; j0 < end; j0 += OW * 32) {
                    int j = j0 + lane;
                    bool pr = j < end;
                    float2 sl = pr ? g_ss_loc[sbase + j] : make_float2(1e30f, 1e30f);
                    float vv  = pr ? g_vs[sbase + j] : 0.f;
                    int fidx  = pr ? g_ss_idx[sbase + j] : 0;
                    float wt[TT];
                    bool anyv = false;
#pragma unroll
                    for (int t = 0; t < TT; t++) {
                        float dx = tx[t] - sl.x, dy = ty[t] - sl.y;
                        float d2 = __fadd_rn(__fmul_rn(dx, dx), __fmul_rn(dy, dy));
                        bool val = d2 < THR2;
                        wt[t] = val ? __expf(__fmul_rn(d2, NEG_INV_SCALE) + tu[t] + vv) : 0.f;
                        anyv |= val;
                    }
                    unsigned bal = __ballot_sync(0xffffffffu, anyv);
                    if (anyv) {
                        int pos = __popc(bal & ((1u << lane) - 1u));
                        sm.outp.fi[wid][pos] = fidx;
#pragma unroll
                        for (int t = 0; t < TT; t++) sm.outp.w[wid][pos][t] = wt[t];
                    }
                    __syncwarp();
                    int ns = __popc(bal);
                    int e = 0;
                    for (; e + 4 <= ns; e += 4) {
                        int fj0 = sm.outp.fi[wid][e],     fj1 = sm.outp.fi[wid][e + 1];
                        int fj2 = sm.outp.fi[wid][e + 2], fj3 = sm.outp.fi[wid][e + 3];
                        float4 a0 = f4[(size_t)fj0 * (CC / 4) + lane];
                        float4 a1 = f4[(size_t)fj1 * (CC / 4) + lane];
                        float4 a2 = f4[(size_t)fj2 * (CC / 4) + lane];
                        float4 a3 = f4[(size_t)fj3 * (CC / 4) + lane];
#pragma unroll
                        for (int t = 0; t < TT; t++) {
                            float w0 = sm.outp.w[wid][e][t],     w1 = sm.outp.w[wid][e + 1][t];
                            float w2 = sm.outp.w[wid][e + 2][t], w3 = sm.outp.w[wid][e + 3][t];
                            acc[t].x = fmaf(w0, a0.x, acc[t].x); acc[t].y = fmaf(w0, a0.y, acc[t].y);
                            acc[t].z = fmaf(w0, a0.z, acc[t].z); acc[t].w = fmaf(w0, a0.w, acc[t].w);
                            acc[t].x = fmaf(w1, a1.x, acc[t].x); acc[t].y = fmaf(w1, a1.y, acc[t].y);
                            acc[t].z = fmaf(w1, a1.z, acc[t].z); acc[t].w = fmaf(w1, a1.w, acc[t].w);
                            acc[t].x = fmaf(w2, a2.x, acc[t].x); acc[t].y = fmaf(w2, a2.y, acc[t].y);
                            acc[t].z = fmaf(w2, a2.z, acc[t].z); acc[t].w = fmaf(w2, a2.w, acc[t].w);
                            acc[t].x = fmaf(w3, a3.x, acc[t].x); acc[t].y = fmaf(w3, a3.y, acc[t].y);
                            acc[t].z = fmaf(w3, a3.z, acc[t].z); acc[t].w = fmaf(w3, a3.w, acc[t].w);
                        }
                    }
                    for (; e < ns; e++) {
                        int fj = sm.outp.fi[wid][e];
                        float4 a = f4[(size_t)fj * (CC / 4) + lane];
#pragma unroll
                        for (int t = 0; t < TT; t++) {
                            float w = sm.outp.w[wid][e][t];
                            acc[t].x = fmaf(w, a.x, acc[t].x); acc[t].y = fmaf(w, a.y, acc[t].y);
                            acc[t].z = fmaf(w, a.z, acc[t].z); acc[t].w = fmaf(w, a.w, acc[t].w);
                        }
                    }
                    __syncwarp();
                }
            }
            // block reduce partials -> out
#pragma unroll
            for (int t = 0; t < TT; t++)
                sm.outp.red4[(wid * TT + t) * 32 + lane] = acc[t];
            __syncthreads();
            for (int t = wid; t < nT; t += OW) {
                float4 a0 = sm.outp.red4[(0 * TT + t) * 32 + lane];
                float4 a1 = sm.outp.red4[(1 * TT + t) * 32 + lane];
                float4 a2 = sm.outp.red4[(2 * TT + t) * 32 + lane];
                float4 a3 = sm.outp.red4[(3 * TT + t) * 32 + lane];
                float4 r;
                r.x = (a0.x + a1.x) + (a2.x + a3.x);
                r.y = (a0.y + a1.y) + (a2.y + a3.y);
                r.z = (a0.z + a1.z) + (a2.z + a3.z);
                r.w = (a0.w + a1.w) + (a2.w + a3.w);
                ((float4*)out)[((size_t)tbase + tidx[t]) * (CC / 4) + lane] = r;
            }
            __syncthreads();
        }
    }
}

// ---------------- launch ----------------
extern "C" void kernel_launch(void* const* d_in, const int* in_sizes, int n_in,
                              void* d_out, int out_size) {
    const float* feats = (const float*)d_in[0];
    const float* slocs = (const float*)d_in[1];
    const float* tlocs = (const float*)d_in[2];
    const void*  smask = d_in[3];
    const void*  tmask = d_in[4];
    float* out = (float*)d_out;

    k_fused<<<GRID, 128>>>(feats, slocs, tlocs, smask, tmask, out);
}